// round 3
// baseline (speedup 1.0000x reference)
#include <cuda_runtime.h>
#include <cuda_bf16.h>
#include <cstdint>

// ============================================================================
// out[b,n,m] = sum_e A[b,n,e] * B[b,m,e]   (b=8, n=m=2048, e=1024, fp32)
//
// sm_103 base target (no 'a' suffix => NO tcgen05). Strategy:
//   Phase 1: convert fp32 -> bf16 hi/lo split into __device__ scratch.
//   Phase 2: mma.sync bf16 GEMM, 3-pass split (hi*hi + hi*lo + lo*hi),
//            cp.async 3-stage pipeline + ldmatrix, 128x128 CTA tiles.
// ============================================================================

static constexpr int BATCH = 8;
static constexpr int NN    = 2048;
static constexpr int MM    = 2048;
static constexpr int E     = 1024;

static constexpr int BM = 128;           // CTA tile: output rows (n dim)
static constexpr int BN = 128;           // CTA tile: output cols (m dim)
static constexpr int BK = 32;            // k per stage (bf16 elements)
static constexpr int STAGES = 3;
static constexpr int NCHUNK = E / BK;    // 32
static constexpr int THREADS = 256;

static constexpr size_t NELEM = (size_t)BATCH * NN * E;  // 16,777,216

// Scratch: bf16 hi/lo copies of both inputs (134 MB total, static device mem)
__device__ __align__(16) __nv_bfloat16 gAhi[NELEM];
__device__ __align__(16) __nv_bfloat16 gAlo[NELEM];
__device__ __align__(16) __nv_bfloat16 gBhi[NELEM];
__device__ __align__(16) __nv_bfloat16 gBlo[NELEM];

static constexpr int TILE_B  = BM * BK * 2;      // 8192 B per tile (128 rows x 64B)
static constexpr int STAGE_B = 4 * TILE_B;       // 32 KB (Ahi, Alo, Bhi, Blo)
static constexpr int SMEM_B  = STAGES * STAGE_B; // 96 KB

#define DINLINE __device__ __forceinline__

DINLINE uint32_t smem_u32(const void* p) {
    uint32_t a;
    asm("{ .reg .u64 t; cvta.to.shared.u64 t, %1; cvt.u32.u64 %0, t; }"
        : "=r"(a) : "l"(p));
    return a;
}

DINLINE void cp_async16(uint32_t dst, const void* src) {
    asm volatile("cp.async.cg.shared.global [%0], [%1], 16;"
                 :: "r"(dst), "l"(src) : "memory");
}
DINLINE void cp_commit() {
    asm volatile("cp.async.commit_group;" ::: "memory");
}
DINLINE void cp_wait1() {
    asm volatile("cp.async.wait_group 1;" ::: "memory");
}

DINLINE void ldsm_x4(uint32_t* r, uint32_t addr) {
    asm volatile("ldmatrix.sync.aligned.m8n8.x4.shared.b16 {%0,%1,%2,%3}, [%4];"
                 : "=r"(r[0]), "=r"(r[1]), "=r"(r[2]), "=r"(r[3]) : "r"(addr));
}

DINLINE void mma_bf16(float* c, const uint32_t* a, const uint32_t* b) {
    asm volatile(
        "mma.sync.aligned.m16n8k16.row.col.f32.bf16.bf16.f32 "
        "{%0,%1,%2,%3}, {%4,%5,%6,%7}, {%8,%9}, {%0,%1,%2,%3};"
        : "+f"(c[0]), "+f"(c[1]), "+f"(c[2]), "+f"(c[3])
        : "r"(a[0]), "r"(a[1]), "r"(a[2]), "r"(a[3]), "r"(b[0]), "r"(b[1]));
}

// ============================================================================
// Phase 1: fp32 -> bf16 hi/lo split. One float4 per thread.
// ============================================================================
__global__ void __launch_bounds__(256)
convert_kernel(const float* __restrict__ src, int which) {
    __nv_bfloat16* hi = which ? gBhi : gAhi;
    __nv_bfloat16* lo = which ? gBlo : gAlo;
    size_t i = (size_t)blockIdx.x * 256 + threadIdx.x;     // float4 index
    float4 v = reinterpret_cast<const float4*>(src)[i];

    __nv_bfloat16 hx = __float2bfloat16_rn(v.x);
    __nv_bfloat16 hy = __float2bfloat16_rn(v.y);
    __nv_bfloat16 hz = __float2bfloat16_rn(v.z);
    __nv_bfloat16 hw = __float2bfloat16_rn(v.w);
    float rx = v.x - __bfloat162float(hx);
    float ry = v.y - __bfloat162float(hy);
    float rz = v.z - __bfloat162float(hz);
    float rw = v.w - __bfloat162float(hw);
    __nv_bfloat16 lx = __float2bfloat16_rn(rx);
    __nv_bfloat16 ly = __float2bfloat16_rn(ry);
    __nv_bfloat16 lz = __float2bfloat16_rn(rz);
    __nv_bfloat16 lw = __float2bfloat16_rn(rw);

    uint32_t h01 = (uint32_t)__bfloat16_as_ushort(hx) |
                   ((uint32_t)__bfloat16_as_ushort(hy) << 16);
    uint32_t h23 = (uint32_t)__bfloat16_as_ushort(hz) |
                   ((uint32_t)__bfloat16_as_ushort(hw) << 16);
    uint32_t l01 = (uint32_t)__bfloat16_as_ushort(lx) |
                   ((uint32_t)__bfloat16_as_ushort(ly) << 16);
    uint32_t l23 = (uint32_t)__bfloat16_as_ushort(lz) |
                   ((uint32_t)__bfloat16_as_ushort(lw) << 16);

    *reinterpret_cast<uint2*>(hi + 4 * i) = make_uint2(h01, h23);
    *reinterpret_cast<uint2*>(lo + 4 * i) = make_uint2(l01, l23);
}

// ============================================================================
// Phase 2: bf16 split GEMM via mma.sync, cp.async 3-stage pipeline.
// Warp layout: 8 warps as 2(m) x 4(n); each warp computes 64x32.
// Smem tile rows are 64B (32 bf16); swizzle: chunk c ^= (row>>1)&3.
// ============================================================================
__global__ void __launch_bounds__(THREADS)
gemm_kernel(float* __restrict__ gC) {
    extern __shared__ char sm[];
    const int tid  = threadIdx.x;
    const int wid  = tid >> 5;
    const int lane = tid & 31;

    const int m0 = blockIdx.x * BN;
    const int n0 = blockIdx.y * BM;
    const int bz = blockIdx.z;
    const int wm = wid >> 2;    // 0..1 -> m-offset wm*64
    const int wn = wid & 3;     // 0..3 -> n-offset wn*32

    const __nv_bfloat16* Ahi = gAhi + ((size_t)bz * NN + n0) * E;
    const __nv_bfloat16* Alo = gAlo + ((size_t)bz * NN + n0) * E;
    const __nv_bfloat16* Bhi = gBhi + ((size_t)bz * MM + m0) * E;
    const __nv_bfloat16* Blo = gBlo + ((size_t)bz * MM + m0) * E;

    const uint32_t smb = smem_u32(sm);

    // cp.async coords: per tile 512 x 16B transfers; 2 per thread per tile.
    const int r0 = tid >> 2;          // row of transfer 0 (transfer 1: +64)
    const int c0 = tid & 3;           // 16B chunk within 64B row

    auto issue = [&](int kc, int buf) {
        const uint32_t sb = smb + buf * STAGE_B;
        const __nv_bfloat16* srcs[4] = {Ahi, Alo, Bhi, Blo};
#pragma unroll
        for (int t = 0; t < 4; t++) {
#pragma unroll
            for (int i = 0; i < 2; i++) {
                int row = r0 + i * 64;
                int cs  = c0 ^ ((row >> 1) & 3);
                uint32_t dst = sb + t * TILE_B + row * 64 + cs * 16;
                const void* src = srcs[t] + (size_t)row * E + kc * BK + c0 * 8;
                cp_async16(dst, src);
            }
        }
    };

    float acc[4][4][4];
#pragma unroll
    for (int a = 0; a < 4; a++)
#pragma unroll
        for (int b = 0; b < 4; b++)
#pragma unroll
            for (int c = 0; c < 4; c++) acc[a][b][c] = 0.0f;

    // Pipeline prologue
#pragma unroll
    for (int s = 0; s < STAGES - 1; s++) { issue(s, s); cp_commit(); }

    for (int kc = 0; kc < NCHUNK; kc++) {
        cp_wait1();
        __syncthreads();
        if (kc + STAGES - 1 < NCHUNK)
            issue(kc + STAGES - 1, (kc + STAGES - 1) % STAGES);
        cp_commit();

        const uint32_t sb = smb + (kc % STAGES) * STAGE_B;
#pragma unroll
        for (int ks = 0; ks < 2; ks++) {
            uint32_t ahi[4][4], alo[4][4], bhi[2][4], blo[2][4];
            // A fragments (m16k16 each): lanes 0-15 -> rows, lane>>4 -> k-half
#pragma unroll
            for (int f = 0; f < 4; f++) {
                int row = wm * 64 + f * 16 + (lane & 15);
                int ch  = ks * 2 + (lane >> 4);
                int cs  = ch ^ ((row >> 1) & 3);
                uint32_t a = sb + row * 64 + cs * 16;
                ldsm_x4(ahi[f], a);
                ldsm_x4(alo[f], a + TILE_B);
            }
            // B fragments: each ldsm.x4 covers 2 n8-frags x k16
#pragma unroll
            for (int p = 0; p < 2; p++) {
                int fi  = p * 2 + (lane >> 4);
                int row = wn * 32 + fi * 8 + (lane & 7);
                int ch  = ks * 2 + ((lane >> 3) & 1);
                int cs  = ch ^ ((row >> 1) & 3);
                uint32_t b = sb + 2 * TILE_B + row * 64 + cs * 16;
                ldsm_x4(bhi[p], b);
                ldsm_x4(blo[p], b + TILE_B);
            }
            // 3-pass split product
#pragma unroll
            for (int mf = 0; mf < 4; mf++)
#pragma unroll
                for (int nf = 0; nf < 4; nf++) {
                    const uint32_t* bh = &bhi[nf >> 1][(nf & 1) * 2];
                    const uint32_t* bl = &blo[nf >> 1][(nf & 1) * 2];
                    mma_bf16(acc[mf][nf], ahi[mf], bh);
                    mma_bf16(acc[mf][nf], ahi[mf], bl);
                    mma_bf16(acc[mf][nf], alo[mf], bh);
                }
        }
    }

    // Epilogue: c-frag layout m16n8: c0,c1 @ (row=lane>>2, col=2*(lane&3)),
    // c2,c3 @ row+8.
#pragma unroll
    for (int mf = 0; mf < 4; mf++) {
        int row = n0 + wm * 64 + mf * 16 + (lane >> 2);
        float* rp = gC + ((size_t)bz * NN + row) * MM;
#pragma unroll
        for (int nf = 0; nf < 4; nf++) {
            int col = m0 + wn * 32 + nf * 8 + 2 * (lane & 3);
            *reinterpret_cast<float2*>(rp + col) =
                make_float2(acc[mf][nf][0], acc[mf][nf][1]);
            *reinterpret_cast<float2*>(rp + (size_t)8 * MM + col) =
                make_float2(acc[mf][nf][2], acc[mf][nf][3]);
        }
    }
}

// ============================================================================
extern "C" void kernel_launch(void* const* d_in, const int* in_sizes, int n_in,
                              void* d_out, int out_size) {
    const float* A = (const float*)d_in[0];   // mat_0 [8, 2048, 1024]
    const float* B = (const float*)d_in[1];   // mat_1 [8, 2048, 1024]
    float* C = (float*)d_out;                 // [8, 2048, 2048]

    cudaFuncSetAttribute(gemm_kernel,
                         cudaFuncAttributeMaxDynamicSharedMemorySize, SMEM_B);

    const int cvt_blocks = (int)(NELEM / 4 / 256);   // 16384
    convert_kernel<<<cvt_blocks, 256>>>(A, 0);
    convert_kernel<<<cvt_blocks, 256>>>(B, 1);

    dim3 grid(MM / BN, NN / BM, BATCH);   // (16, 16, 8)
    gemm_kernel<<<grid, THREADS, SMEM_B>>>(C);
}